// round 16
// baseline (speedup 1.0000x reference)
#include <cuda_runtime.h>

// Problem constants (fixed by the dataset)
#define CC     24
#define NPTS   1536
#define HV     40
#define EPSF   1e-8f
#define T_PEN  0.1f
#define R_PEN  1.0f
#define BLK    256
#define HALVES 2
#define PPT    (NPTS / HALVES / BLK)   // 3 points per thread
#define FINF   3.4e38f

// ---------------------------------------------------------------------------
// Device scratch (no allocations allowed)
// ---------------------------------------------------------------------------
__device__ float4 g_xf   [CC];        // ca, sa, tx2, ty2 (folded transform)
__device__ float4 g_edges[CC * HV];   // ex, -ey, -c0, 1/(len+eps) (compacted)
__device__ int    g_nv   [CC];        // valid edge count
__device__ float4 g_hbb  [CC];        // expanded hull bbox

// ---------------------------------------------------------------------------
// Stage A: ONE block, 256 threads. All per-cluster precompute:
//  - folded transform constants (sincos once per cluster)
//  - transformed hulls -> compacted edges -> expanded hull bboxes
//  - rotation+translation penalty -> out[0] (re-inits accumulator per replay)
// ---------------------------------------------------------------------------
__global__ __launch_bounds__(BLK)
void csep_setup(const float2* __restrict__ hulls,
                const float2* __restrict__ medoids,
                const float*  __restrict__ angles,
                const float2* __restrict__ trans,
                float* __restrict__ out) {
    const int tid = threadIdx.x;

    __shared__ float4 sxf[CC];
    __shared__ float2 shull[CC * HV];   // 7.5 KB
    __shared__ int    snv[CC];

    float pen = 0.0f;
    if (tid < CC) {
        float a = angles[tid];
        float sv, cv;
        sincosf(a, &sv, &cv);
        float2 m = medoids[tid];
        float2 t = trans[tid];
        float ox = m.x + t.x, oy = m.y + t.y;
        // px = cv*x - sv*y + tx2 ; py = sv*x + cv*y + ty2
        float tx2 = ox - cv * m.x + sv * m.y;
        float ty2 = oy - sv * m.x - cv * m.y;
        float4 xf = make_float4(cv, sv, tx2, ty2);
        g_xf[tid] = xf;
        sxf[tid]  = xf;
        snv[tid]  = 0;
        pen = R_PEN * a * a + T_PEN * (t.x * t.x + t.y * t.y);
    }
    // penalty reduction (warp 0; lanes >= CC contribute 0)
    if (tid < 32) {
        #pragma unroll
        for (int o = 16; o > 0; o >>= 1)
            pen += __shfl_down_sync(0xffffffffu, pen, o);
        if (tid == 0) out[0] = pen;
    }
    __syncthreads();

    // transform all hull vertices (24*40 = 960)
    for (int idx = tid; idx < CC * HV; idx += BLK) {
        int c = idx / HV;
        float4 xf = sxf[c];
        float2 h = hulls[idx];
        shull[idx] = make_float2(xf.x * h.x - xf.y * h.y + xf.z,
                                 xf.y * h.x + xf.x * h.y + xf.w);
    }
    __syncthreads();

    // edges: compact valid ones per cluster (shared atomics)
    for (int idx = tid; idx < CC * HV; idx += BLK) {
        int c = idx / HV, v = idx - c * HV;
        float2 p1 = shull[idx];
        float2 p2 = shull[c * HV + ((v + 1 == HV) ? 0 : v + 1)];
        float ex = p2.x - p1.x, ey = p2.y - p1.y;
        float len = sqrtf(ex * ex + ey * ey);
        if (len > 1e-6f) {                         // evalid (reference-exact)
            int k = atomicAdd(&snv[c], 1);
            g_edges[c * HV + k] = make_float4(ex, -ey,
                                              -(ex * p1.y - ey * p1.x),
                                              1.0f / (len + EPSF));
        }
    }

    // expanded hull bboxes (one thread per cluster; independent of edge pass)
    if (tid < CC) {
        const float2* hv = shull + tid * HV;
        float x0 = hv[0].x, x1 = x0, y0 = hv[0].y, y1 = y0;
        #pragma unroll
        for (int k = 1; k < HV; ++k) {
            float2 q = hv[k];
            x0 = fminf(x0, q.x); x1 = fmaxf(x1, q.x);
            y0 = fminf(y0, q.y); y1 = fmaxf(y1, q.y);
        }
        const float M = 0.05f;   // margin >> fp error of signed distance
        g_hbb[tid] = make_float4(x0 - M, x1 + M, y0 - M, y1 + M);
    }
    __syncthreads();
    if (tid < CC) g_nv[tid] = snv[tid];
}

// ---------------------------------------------------------------------------
// Stage B: grid (HALVES, j, i) = 1152 blocks, 3 points/thread.
//  - inline point transform (4 FMA) using folded constants
//  - per-point bbox test (exact prefilter), block-level __syncthreads_or exit
//  - single shared-edge pass evaluates all 3 points per edge load
// ---------------------------------------------------------------------------
__global__ __launch_bounds__(BLK)
void csep_pairs(const float2* __restrict__ pts, float* __restrict__ out) {
    const int half = blockIdx.x;
    const int j    = blockIdx.y;
    const int i    = blockIdx.z;
    if (i == j) return;

    const int nv = g_nv[j];
    if (nv < 3) return;                  // hull_ok false

    __shared__ float4 sedge[HV];
    __shared__ float  swsum[BLK / 32];

    const int tid = threadIdx.x;
    const float4 hb = g_hbb[j];
    const float4 xf = g_xf[i];

    if (tid < nv) sedge[tid] = g_edges[j * HV + tid];

    // 3 coalesced raw point loads (all in flight)
    const float2* base = pts + i * NPTS + half * (NPTS / HALVES);
    float2 p0 = base[tid];
    float2 p1 = base[tid + BLK];
    float2 p2 = base[tid + 2 * BLK];

    // inline transform; padded points are exact (0,0) -> sentinel
    float px0, py0, px1, py1, px2, py2;
    {
        px0 = xf.x * p0.x - xf.y * p0.y + xf.z;
        py0 = xf.y * p0.x + xf.x * p0.y + xf.w;
        if (p0.x == 0.0f && p0.y == 0.0f) { px0 = 1e30f; py0 = 1e30f; }
        px1 = xf.x * p1.x - xf.y * p1.y + xf.z;
        py1 = xf.y * p1.x + xf.x * p1.y + xf.w;
        if (p1.x == 0.0f && p1.y == 0.0f) { px1 = 1e30f; py1 = 1e30f; }
        px2 = xf.x * p2.x - xf.y * p2.y + xf.z;
        py2 = xf.y * p2.x + xf.x * p2.y + xf.w;
        if (p2.x == 0.0f && p2.y == 0.0f) { px2 = 1e30f; py2 = 1e30f; }
    }

    const bool b0 = (px0 >= hb.x) & (px0 <= hb.y) & (py0 >= hb.z) & (py0 <= hb.w);
    const bool b1 = (px1 >= hb.x) & (px1 <= hb.y) & (py1 >= hb.z) & (py1 <= hb.w);
    const bool b2 = (px2 >= hb.x) & (px2 <= hb.y) & (py2 >= hb.z) & (py2 <= hb.w);

    if (!__syncthreads_or(b0 | b1 | b2)) return;   // exact; also fences sedge

    float local = 0.0f;
    if (b0 | b1 | b2) {
        float mn0 = FINF, mx0 = -FINF;
        float mn1 = FINF, mx1 = -FINF;
        float mn2 = FINF, mx2 = -FINF;
        #pragma unroll 4
        for (int e = 0; e < nv; ++e) {
            float4 ed = sedge[e];                    // one LDS.128 for 3 points
            float s0 = fmaf(ed.y, px0, fmaf(ed.x, py0, ed.z)) * ed.w;
            float s1 = fmaf(ed.y, px1, fmaf(ed.x, py1, ed.z)) * ed.w;
            float s2 = fmaf(ed.y, px2, fmaf(ed.x, py2, ed.z)) * ed.w;
            mn0 = fminf(mn0, s0); mx0 = fmaxf(mx0, s0);
            mn1 = fminf(mn1, s1); mx1 = fmaxf(mx1, s1);
            mn2 = fminf(mn2, s2); mx2 = fmaxf(mx2, s2);
        }
        if (b0) {
            bool pos = (mn0 >= -EPSF), neg = (mx0 <= EPSF);
            if (pos | neg)
                local += __fdividef(1.0f, 1.0f + __expf(-(pos ? fabsf(mn0) : fabsf(mx0))));
        }
        if (b1) {
            bool pos = (mn1 >= -EPSF), neg = (mx1 <= EPSF);
            if (pos | neg)
                local += __fdividef(1.0f, 1.0f + __expf(-(pos ? fabsf(mn1) : fabsf(mx1))));
        }
        if (b2) {
            bool pos = (mn2 >= -EPSF), neg = (mx2 <= EPSF);
            if (pos | neg)
                local += __fdividef(1.0f, 1.0f + __expf(-(pos ? fabsf(mn2) : fabsf(mx2))));
        }
    }

    // block reduction + single atomic
    #pragma unroll
    for (int o = 16; o > 0; o >>= 1)
        local += __shfl_down_sync(0xffffffffu, local, o);
    const int wid = tid >> 5, lid = tid & 31;
    if (lid == 0) swsum[wid] = local;
    __syncthreads();
    if (wid == 0) {
        float v = (lid < (BLK / 32)) ? swsum[lid] : 0.0f;
        #pragma unroll
        for (int o = (BLK / 64); o > 0; o >>= 1)
            v += __shfl_down_sync(0xffffffffu, v, o);
        if (lid == 0 && v != 0.0f)
            atomicAdd(out, v);               // SEP_W == 1.0
    }
}

// ---------------------------------------------------------------------------
// Launch. Inputs (metadata order):
//  0: padded_clusters (C,N,2) f32   1: padded_hulls (C,H,2) f32
//  2: medoids (C,2) f32             3: rotation_angles (C,) f32
//  4: translations (C,2) f32        5: cluster_masks (unused)
//  6: hull_masks (unused)
// ---------------------------------------------------------------------------
extern "C" void kernel_launch(void* const* d_in, const int* in_sizes, int n_in,
                              void* d_out, int out_size) {
    const float2* pts     = (const float2*)d_in[0];
    const float2* hulls   = (const float2*)d_in[1];
    const float2* medoids = (const float2*)d_in[2];
    const float*  angles  = (const float*) d_in[3];
    const float2* trans   = (const float2*)d_in[4];
    float* out = (float*)d_out;

    csep_setup<<<1, BLK>>>(hulls, medoids, angles, trans, out);

    dim3 g2(HALVES, CC, CC);
    csep_pairs<<<g2, BLK>>>(pts, out);
}